// round 14
// baseline (speedup 1.0000x reference)
#include <cuda_runtime.h>
#include <cuda_bf16.h>
#include <mma.h>
#include <cstdint>

using namespace nvcuda;

// Problem constants (fixed by the dataset instance)
static constexpr int T_TOK = 2048;
static constexpr int HS    = 2048;
static constexpr int IMZ   = 1408;
static constexpr int NE    = 32;

// Tiling
static constexpr int BM = 64;
static constexpr int BN = 128;
static constexpr int BK = 32;
static constexpr int NTHREADS = 512;      // 8 MMA warps + 8 producer warps
static constexpr int LDA = BK + 8;        // 40 bf16 elems
static constexpr int LDB = BN + 8;        // 136 bf16 elems

// Stage: A hi/lo 2*5120B + B hi/lo 2*8704B = 27648B; double-buffered.
static constexpr int GEMM_STAGE = 27648;
static constexpr int GEMM_SMEM  = 2 * GEMM_STAGE;   // 55296
// Epilogue staging tile (aliases stage 0/1): 64*136*4 = 34816 <= 55296.

// Scratch (static device allocations are allowed; cudaMalloc is not)
__device__ float g_gate [(size_t)T_TOK * IMZ];
__device__ float g_up   [(size_t)T_TOK * IMZ];
__device__ float g_inter[(size_t)T_TOK * IMZ];

// ---------------------------------------------------------------------------
// fp32 x8 -> bf16 hi/lo split, packed as uint4 (8 bf16 = 16B) for STS.128.
// hi = rn(x), lo = rn(x - hi). bf16x3 product error ~2^-16 rel.
// ---------------------------------------------------------------------------
__device__ __forceinline__ void split8(const float4& a, const float4& b,
                                       uint4& hi, uint4& lo) {
    __nv_bfloat162 h0 = __floats2bfloat162_rn(a.x, a.y);
    __nv_bfloat162 h1 = __floats2bfloat162_rn(a.z, a.w);
    __nv_bfloat162 h2 = __floats2bfloat162_rn(b.x, b.y);
    __nv_bfloat162 h3 = __floats2bfloat162_rn(b.z, b.w);
    float2 f0 = __bfloat1622float2(h0);
    float2 f1 = __bfloat1622float2(h1);
    float2 f2 = __bfloat1622float2(h2);
    float2 f3 = __bfloat1622float2(h3);
    __nv_bfloat162 l0 = __floats2bfloat162_rn(a.x - f0.x, a.y - f0.y);
    __nv_bfloat162 l1 = __floats2bfloat162_rn(a.z - f1.x, a.w - f1.y);
    __nv_bfloat162 l2 = __floats2bfloat162_rn(b.x - f2.x, b.y - f2.y);
    __nv_bfloat162 l3 = __floats2bfloat162_rn(b.z - f3.x, b.w - f3.y);
    hi.x = *(const uint32_t*)&h0; hi.y = *(const uint32_t*)&h1;
    hi.z = *(const uint32_t*)&h2; hi.w = *(const uint32_t*)&h3;
    lo.x = *(const uint32_t*)&l0; lo.y = *(const uint32_t*)&l1;
    lo.z = *(const uint32_t*)&l2; lo.w = *(const uint32_t*)&l3;
}

// ---------------------------------------------------------------------------
// Warp-specialized grouped GEMM.  Warps 0-7: LDSM+HMMA only (dense tensor
// issue stream).  Warps 8-15: LDG prefetch + fp32->bf16 hi/lo split + STS.
// Tile pool can span two weight/output pairs (gate+up in one launch).
// A: [T, K] fp32.  B: [E, K, NTOT] fp32 (n contiguous).  bf16x3 via HMMA,
// 2-stage smem pipeline, one barrier per k-iter.  Grid = tile count.
// ---------------------------------------------------------------------------
__global__ __launch_bounds__(NTHREADS, 1)
void gemm_tc(const float* __restrict__ A,
             const float* __restrict__ B1, float* __restrict__ Out1,
             const float* __restrict__ B2, float* __restrict__ Out2,
             const int* __restrict__ gs,
             int K, int NTOT, int nx, int ntiles_per)
{
    extern __shared__ __align__(16) char ds[];
    __shared__ int s_ofs[NE + 1];

#define S_AHI(s) ((__nv_bfloat16*)(ds + (s) * GEMM_STAGE))
#define S_ALO(s) ((__nv_bfloat16*)(ds + (s) * GEMM_STAGE + 5120))
#define S_BHI(s) ((__nv_bfloat16*)(ds + (s) * GEMM_STAGE + 10240))
#define S_BLO(s) ((__nv_bfloat16*)(ds + (s) * GEMM_STAGE + 18944))
    float* sStage = (float*)ds;  // epilogue staging (after final bar)

    const int tid = threadIdx.x;
    const int wid = tid >> 5;
    const bool is_mma = (wid < 8);
    // MMA-warp coords (warps 0-7): 2 (m) x 4 (n)
    const int warp_m = (wid >> 2) & 1;
    const int warp_n = wid & 3;
    // Producer coords (warps 8-15): pid in [0,256)
    const int pid = tid - 256;
    const int rA = pid >> 2;            // 0..63
    const int cA = (pid & 3) * 8;       // 0..24
    const int rB = pid >> 4;            // 0..15 (+16 for group 1)
    const int cB = (pid & 15) * 8;      // 0..120

    // Expert-offset prefix.
    if (tid < 32) {
        int g = (tid < NE) ? gs[tid] : 0;
        int v = g;
#pragma unroll
        for (int d = 1; d < 32; d <<= 1) {
            int t = __shfl_up_sync(0xffffffffu, v, d);
            if (tid >= d) v += t;
        }
        if (tid < NE) s_ofs[tid + 1] = v;
        if (tid == 0) s_ofs[0] = 0;
    }
    __syncthreads();

    // Tile select (pool may span two GEMMs)
    int t = blockIdx.x;
    const float* B   = (t < ntiles_per) ? B1 : B2;
    float*       Out = (t < ntiles_per) ? Out1 : Out2;
    if (t >= ntiles_per) t -= ntiles_per;

    const int e  = t / nx;
    const int n0 = (t - e * nx) * BN;
    const int off0 = s_ofs[e], off1 = s_ofs[e + 1];
    const float* wb = B + (size_t)e * K * NTOT + n0;

    const int NS = K >> 5;              // K / BK

    // Producer prefetch registers (only producers touch these)
    float4 a0, a1, bb[2][2];

    for (int row_base = off0; row_base < off1; row_base += BM) {
        const int rows = min(BM, off1 - row_base);

        wmma::fragment<wmma::accumulator, 16, 16, 16, float> acc[2][2];
        if (is_mma) {
#pragma unroll
            for (int m = 0; m < 2; ++m)
#pragma unroll
                for (int n = 0; n < 2; ++n) wmma::fill_fragment(acc[m][n], 0.0f);
        } else {
            // ---- producer prologue: tile 0 -> regs -> buf0; tile 1 -> regs ----
            const float* arow = A + (size_t)(row_base + rA) * K + cA;
            if (rA < rows) { a0 = *(const float4*)arow; a1 = *(const float4*)(arow + 4); }
            else           { a0 = a1 = make_float4(0.f, 0.f, 0.f, 0.f); }
#pragma unroll
            for (int i = 0; i < 2; ++i) {
                const float* brow = wb + (size_t)(rB + 16 * i) * NTOT + cB;
                bb[i][0] = *(const float4*)brow;
                bb[i][1] = *(const float4*)(brow + 4);
            }
            {
                uint4 hi, lo;
                split8(a0, a1, hi, lo);
                *(uint4*)(S_AHI(0) + rA * LDA + cA) = hi;
                *(uint4*)(S_ALO(0) + rA * LDA + cA) = lo;
#pragma unroll
                for (int i = 0; i < 2; ++i) {
                    split8(bb[i][0], bb[i][1], hi, lo);
                    *(uint4*)(S_BHI(0) + (rB + 16 * i) * LDB + cB) = hi;
                    *(uint4*)(S_BLO(0) + (rB + 16 * i) * LDB + cB) = lo;
                }
            }
            if (NS > 1) {
                if (rA < rows) { a0 = *(const float4*)(arow + BK); a1 = *(const float4*)(arow + BK + 4); }
                else           { a0 = a1 = make_float4(0.f, 0.f, 0.f, 0.f); }
#pragma unroll
                for (int i = 0; i < 2; ++i) {
                    const float* brow = wb + (size_t)(BK + rB + 16 * i) * NTOT + cB;
                    bb[i][0] = *(const float4*)brow;
                    bb[i][1] = *(const float4*)(brow + 4);
                }
            }
        }
        __syncthreads();

        for (int k = 0; k < NS; ++k) {
            const int b  = k & 1;
            const int nb = b ^ 1;

            if (is_mma) {
                // ---- MMA warps: LDSM + HMMA only ----
                __nv_bfloat16* sAhi = S_AHI(b); __nv_bfloat16* sAlo = S_ALO(b);
                __nv_bfloat16* sBhi = S_BHI(b); __nv_bfloat16* sBlo = S_BLO(b);
#pragma unroll
                for (int kk = 0; kk < 2; ++kk) {
                    wmma::fragment<wmma::matrix_a, 16, 16, 16, __nv_bfloat16, wmma::row_major> ahi[2], alo[2];
#pragma unroll
                    for (int m = 0; m < 2; ++m) {
                        const int ro = (warp_m * 32 + m * 16) * LDA + kk * 16;
                        wmma::load_matrix_sync(ahi[m], sAhi + ro, LDA);
                        wmma::load_matrix_sync(alo[m], sAlo + ro, LDA);
                    }
#pragma unroll
                    for (int n = 0; n < 2; ++n) {
                        const int co = (kk * 16) * LDB + warp_n * 32 + n * 16;
                        wmma::fragment<wmma::matrix_b, 16, 16, 16, __nv_bfloat16, wmma::row_major> bhi, blo;
                        wmma::load_matrix_sync(bhi, sBhi + co, LDB);
                        wmma::load_matrix_sync(blo, sBlo + co, LDB);
#pragma unroll
                        for (int m = 0; m < 2; ++m) {
                            wmma::mma_sync(acc[m][n], ahi[m], bhi, acc[m][n]);
                            wmma::mma_sync(acc[m][n], ahi[m], blo, acc[m][n]);
                            wmma::mma_sync(acc[m][n], alo[m], bhi, acc[m][n]);
                        }
                    }
                }
            } else {
                // ---- producers: split+store tile k+1 into buf nb ----
                if (k + 1 < NS) {
                    uint4 hi, lo;
                    split8(a0, a1, hi, lo);
                    *(uint4*)(S_AHI(nb) + rA * LDA + cA) = hi;
                    *(uint4*)(S_ALO(nb) + rA * LDA + cA) = lo;
#pragma unroll
                    for (int i = 0; i < 2; ++i) {
                        split8(bb[i][0], bb[i][1], hi, lo);
                        *(uint4*)(S_BHI(nb) + (rB + 16 * i) * LDB + cB) = hi;
                        *(uint4*)(S_BLO(nb) + (rB + 16 * i) * LDB + cB) = lo;
                    }
                }
                // ---- prefetch tile k+2 into registers ----
                if (k + 2 < NS) {
                    const int kn = (k + 2) * BK;
                    const float* arow = A + (size_t)(row_base + rA) * K + cA;
                    if (rA < rows) { a0 = *(const float4*)(arow + kn); a1 = *(const float4*)(arow + kn + 4); }
                    else           { a0 = a1 = make_float4(0.f, 0.f, 0.f, 0.f); }
#pragma unroll
                    for (int i = 0; i < 2; ++i) {
                        const float* brow = wb + (size_t)(kn + rB + 16 * i) * NTOT + cB;
                        bb[i][0] = *(const float4*)brow;
                        bb[i][1] = *(const float4*)(brow + 4);
                    }
                }
            }
            __syncthreads();
        }

        // ---- epilogue: MMA warps stage acc, all warps store to global ----
        if (is_mma) {
#pragma unroll
            for (int m = 0; m < 2; ++m)
#pragma unroll
                for (int n = 0; n < 2; ++n)
                    wmma::store_matrix_sync(
                        sStage + (warp_m * 32 + m * 16) * LDB + warp_n * 32 + n * 16,
                        acc[m][n], LDB, wmma::mem_row_major);
        }
        __syncthreads();
#pragma unroll
        for (int i = 0; i < 4; ++i) {
            int id = tid + i * NTHREADS;
            int r  = id >> 5;
            int c  = (id & 31) * 4;
            if (r < rows) {
                float4 v = *(const float4*)(sStage + r * LDB + c);
                *(float4*)(Out + (size_t)(row_base + r) * NTOT + n0 + c) = v;
            }
        }
        __syncthreads();
    }
#undef S_AHI
#undef S_ALO
#undef S_BHI
#undef S_BLO
}

// ---------------------------------------------------------------------------
// Elementwise SwiGLU: inter = silu(gate) * up
// ---------------------------------------------------------------------------
__global__ __launch_bounds__(256)
void swiglu_kernel() {
    constexpr size_t N4 = (size_t)T_TOK * IMZ / 4;
    size_t i = (size_t)blockIdx.x * 256 + threadIdx.x;
    if (i < N4) {
        float4 g = ((const float4*)g_gate)[i];
        float4 u = ((const float4*)g_up)[i];
        float4 o;
        o.x = u.x * g.x / (1.0f + __expf(-g.x));
        o.y = u.y * g.y / (1.0f + __expf(-g.y));
        o.z = u.z * g.z / (1.0f + __expf(-g.z));
        o.w = u.w * g.w / (1.0f + __expf(-g.w));
        ((float4*)g_inter)[i] = o;
    }
}

// ---------------------------------------------------------------------------
extern "C" void kernel_launch(void* const* d_in, const int* in_sizes, int n_in,
                              void* d_out, int out_size) {
    const float* H  = (const float*)d_in[0];   // hidden_states [T, HS]
    const float* Wg = (const float*)d_in[1];   // gate_kernel   [E, HS, IMZ]
    const float* Wu = (const float*)d_in[2];   // up_kernel     [E, HS, IMZ]
    const float* Wd = (const float*)d_in[3];   // down_kernel   [E, IMZ, HS]
    const int*   gs = (const int*)d_in[4];     // group_sizes   [E]
    float* Out = (float*)d_out;                // [T, HS]

    cudaFuncSetAttribute(gemm_tc, cudaFuncAttributeMaxDynamicSharedMemorySize,
                         GEMM_SMEM);

    float* gate_p = nullptr, *up_p = nullptr, *inter_p = nullptr;
    cudaGetSymbolAddress((void**)&gate_p,  g_gate);
    cudaGetSymbolAddress((void**)&up_p,    g_up);
    cudaGetSymbolAddress((void**)&inter_p, g_inter);

    // Gate + Up as ONE tile pool (704 tiles) for load balance.
    const int nt_gu = (IMZ / BN) * NE;   // 352
    gemm_tc<<<2 * nt_gu, NTHREADS, GEMM_SMEM>>>(
        H, Wg, gate_p, Wu, up_p, gs, HS, IMZ, IMZ / BN, nt_gu);

    const int n4 = (int)(((size_t)T_TOK * IMZ / 4 + 255) / 256);
    swiglu_kernel<<<n4, 256>>>();

    // Down: 512 tiles.
    const int nt_dn = (HS / BN) * NE;    // 512
    gemm_tc<<<nt_dn, NTHREADS, GEMM_SMEM>>>(
        inter_p, Wd, Out, Wd, Out, gs, IMZ, HS, HS / BN, nt_dn);
}

// round 15
// speedup vs baseline: 1.1060x; 1.1060x over previous
#include <cuda_runtime.h>
#include <cuda_bf16.h>
#include <mma.h>
#include <cstdint>

using namespace nvcuda;

// Problem constants (fixed by the dataset instance)
static constexpr int T_TOK = 2048;
static constexpr int HS    = 2048;
static constexpr int IMZ   = 1408;
static constexpr int NE    = 32;

// Tiling
static constexpr int BM = 64;
static constexpr int BN = 128;
static constexpr int BK = 32;
static constexpr int NTHREADS = 256;      // 8 warps: 2 (m) x 4 (n)
static constexpr int LDA = BK + 8;        // 40 bf16 elems
static constexpr int LDB = BN + 8;        // 136 bf16 elems

// Stage: A hi/lo 2*5120B + B hi/lo 2*8704B = 27648B; double-buffered.
static constexpr int GEMM_STAGE = 27648;
static constexpr int GEMM_SMEM  = 2 * GEMM_STAGE;   // 55296
// Epilogue staging tile (aliases stage 0/1): 64*136*4 = 34816 <= 55296.

// Scratch (static device allocations are allowed; cudaMalloc is not)
__device__ __nv_bfloat16 g_Ahi[(size_t)T_TOK * HS];
__device__ __nv_bfloat16 g_Alo[(size_t)T_TOK * HS];
__device__ float         g_gate[(size_t)T_TOK * IMZ];
__device__ float         g_up  [(size_t)T_TOK * IMZ];
__device__ __nv_bfloat16 g_Ihi[(size_t)T_TOK * IMZ];
__device__ __nv_bfloat16 g_Ilo[(size_t)T_TOK * IMZ];

// ---------------------------------------------------------------------------
// fp32 x8 -> bf16 hi/lo split, packed as uint4 (8 bf16 = 16B).
// hi = rn(x), lo = rn(x - hi). bf16x3 product error ~2^-16 rel.
// ---------------------------------------------------------------------------
__device__ __forceinline__ void split8(const float4& a, const float4& b,
                                       uint4& hi, uint4& lo) {
    __nv_bfloat162 h0 = __floats2bfloat162_rn(a.x, a.y);
    __nv_bfloat162 h1 = __floats2bfloat162_rn(a.z, a.w);
    __nv_bfloat162 h2 = __floats2bfloat162_rn(b.x, b.y);
    __nv_bfloat162 h3 = __floats2bfloat162_rn(b.z, b.w);
    float2 f0 = __bfloat1622float2(h0);
    float2 f1 = __bfloat1622float2(h1);
    float2 f2 = __bfloat1622float2(h2);
    float2 f3 = __bfloat1622float2(h3);
    __nv_bfloat162 l0 = __floats2bfloat162_rn(a.x - f0.x, a.y - f0.y);
    __nv_bfloat162 l1 = __floats2bfloat162_rn(a.z - f1.x, a.w - f1.y);
    __nv_bfloat162 l2 = __floats2bfloat162_rn(b.x - f2.x, b.y - f2.y);
    __nv_bfloat162 l3 = __floats2bfloat162_rn(b.z - f3.x, b.w - f3.y);
    hi.x = *(const uint32_t*)&h0; hi.y = *(const uint32_t*)&h1;
    hi.z = *(const uint32_t*)&h2; hi.w = *(const uint32_t*)&h3;
    lo.x = *(const uint32_t*)&l0; lo.y = *(const uint32_t*)&l1;
    lo.z = *(const uint32_t*)&l2; lo.w = *(const uint32_t*)&l3;
}

// ---------------------------------------------------------------------------
// Pre-convert H into bf16 hi/lo planes (one streaming pass, ~16MB).
// ---------------------------------------------------------------------------
__global__ __launch_bounds__(256)
void convert_H(const float* __restrict__ H) {
    constexpr size_t N8 = (size_t)T_TOK * HS / 8;
    size_t i = (size_t)blockIdx.x * 256 + threadIdx.x;
    if (i < N8) {
        const float4* p = (const float4*)H + 2 * i;
        float4 a = p[0], b = p[1];
        uint4 hi, lo;
        split8(a, b, hi, lo);
        ((uint4*)g_Ahi)[i] = hi;
        ((uint4*)g_Alo)[i] = lo;
    }
}

// ---------------------------------------------------------------------------
// SwiGLU: inter = silu(gate) * up, emitted directly as bf16 hi/lo planes.
// ---------------------------------------------------------------------------
__global__ __launch_bounds__(256)
void swiglu_kernel() {
    constexpr size_t N8 = (size_t)T_TOK * IMZ / 8;
    size_t i = (size_t)blockIdx.x * 256 + threadIdx.x;
    if (i < N8) {
        const float4* gp = (const float4*)g_gate + 2 * i;
        const float4* up = (const float4*)g_up + 2 * i;
        float4 g0 = gp[0], g1 = gp[1];
        float4 u0 = up[0], u1 = up[1];
        float4 o0, o1;
        o0.x = u0.x * g0.x / (1.0f + __expf(-g0.x));
        o0.y = u0.y * g0.y / (1.0f + __expf(-g0.y));
        o0.z = u0.z * g0.z / (1.0f + __expf(-g0.z));
        o0.w = u0.w * g0.w / (1.0f + __expf(-g0.w));
        o1.x = u1.x * g1.x / (1.0f + __expf(-g1.x));
        o1.y = u1.y * g1.y / (1.0f + __expf(-g1.y));
        o1.z = u1.z * g1.z / (1.0f + __expf(-g1.z));
        o1.w = u1.w * g1.w / (1.0f + __expf(-g1.w));
        uint4 hi, lo;
        split8(o0, o1, hi, lo);
        ((uint4*)g_Ihi)[i] = hi;
        ((uint4*)g_Ilo)[i] = lo;
    }
}

// ---------------------------------------------------------------------------
// Grouped GEMM, A pre-split into bf16 hi/lo planes (LDG.128 -> STS.128, no
// in-loop A conversion).  B split in-loop (weights are single-use).
// Tile pool can span two weight/output pairs (gate+up in one launch).
// bf16x3 via HMMA, 2-stage smem pipeline, register prefetch, one bar/iter.
// Grid = tile count (one tile per CTA; HW work-stealing balances waves).
// ---------------------------------------------------------------------------
__global__ __launch_bounds__(NTHREADS, 2)
void gemm_tc(const __nv_bfloat16* __restrict__ Ahi,
             const __nv_bfloat16* __restrict__ Alo,
             const float* __restrict__ B1, float* __restrict__ Out1,
             const float* __restrict__ B2, float* __restrict__ Out2,
             const int* __restrict__ gs,
             int K, int NTOT, int nx, int ntiles_per)
{
    extern __shared__ __align__(16) char ds[];
    __shared__ int s_ofs[NE + 1];

#define S_AHI(s) ((__nv_bfloat16*)(ds + (s) * GEMM_STAGE))
#define S_ALO(s) ((__nv_bfloat16*)(ds + (s) * GEMM_STAGE + 5120))
#define S_BHI(s) ((__nv_bfloat16*)(ds + (s) * GEMM_STAGE + 10240))
#define S_BLO(s) ((__nv_bfloat16*)(ds + (s) * GEMM_STAGE + 18944))
    float* sStage = (float*)ds;  // epilogue staging (after final bar)

    const int tid = threadIdx.x;
    const int wid = tid >> 5;
    const int warp_m = wid >> 2;   // 0..1 -> 32 rows
    const int warp_n = wid & 3;    // 0..3 -> 32 cols

    // Expert-offset prefix.
    if (tid < 32) {
        int g = (tid < NE) ? gs[tid] : 0;
        int v = g;
#pragma unroll
        for (int d = 1; d < 32; d <<= 1) {
            int t = __shfl_up_sync(0xffffffffu, v, d);
            if (tid >= d) v += t;
        }
        if (tid < NE) s_ofs[tid + 1] = v;
        if (tid == 0) s_ofs[0] = 0;
    }
    __syncthreads();

    // Tile select (pool may span two GEMMs)
    int t = blockIdx.x;
    const float* B   = (t < ntiles_per) ? B1 : B2;
    float*       Out = (t < ntiles_per) ? Out1 : Out2;
    if (t >= ntiles_per) t -= ntiles_per;

    const int e  = t / nx;
    const int n0 = (t - e * nx) * BN;
    const int off0 = s_ofs[e], off1 = s_ofs[e + 1];
    const float* wb = B + (size_t)e * K * NTOT + n0;

    // Per-thread load coords
    const int rA = tid >> 2;            // 0..63
    const int cA = (tid & 3) * 8;       // 0..24
    const int rB = tid >> 4;            // 0..15 (+16 for group 1)
    const int cB = (tid & 15) * 8;      // 0..120

    const int NS = K >> 5;              // K / BK
    const size_t bstep = (size_t)BK * NTOT;

    for (int row_base = off0; row_base < off1; row_base += BM) {
        const int rows = min(BM, off1 - row_base);
        // Clamp instead of branch: padded rows read a valid token row; their
        // outputs land in acc rows that the predicated epilogue discards.
        const int rowc = min(row_base + rA, off1 - 1);

        wmma::fragment<wmma::accumulator, 16, 16, 16, float> acc[2][2];
#pragma unroll
        for (int m = 0; m < 2; ++m)
#pragma unroll
            for (int n = 0; n < 2; ++n) wmma::fill_fragment(acc[m][n], 0.0f);

        const __nv_bfloat16* aph = Ahi + (size_t)rowc * K + cA;
        const __nv_bfloat16* apl = Alo + (size_t)rowc * K + cA;
        const float* bp0 = wb + (size_t)rB * NTOT + cB;
        const float* bp1 = wb + (size_t)(rB + 16) * NTOT + cB;

        uint4 ah, al;
        float4 b00, b01, b10, b11;

        // ---- prologue: tile 0 -> buf0 directly; tile 1 -> regs ----
        ah = *(const uint4*)aph;  al = *(const uint4*)apl;
        b00 = *(const float4*)bp0; b01 = *(const float4*)(bp0 + 4);
        b10 = *(const float4*)bp1; b11 = *(const float4*)(bp1 + 4);
        *(uint4*)(S_AHI(0) + rA * LDA + cA) = ah;
        *(uint4*)(S_ALO(0) + rA * LDA + cA) = al;
        {
            uint4 hi, lo;
            split8(b00, b01, hi, lo);
            *(uint4*)(S_BHI(0) + rB * LDB + cB) = hi;
            *(uint4*)(S_BLO(0) + rB * LDB + cB) = lo;
            split8(b10, b11, hi, lo);
            *(uint4*)(S_BHI(0) + (rB + 16) * LDB + cB) = hi;
            *(uint4*)(S_BLO(0) + (rB + 16) * LDB + cB) = lo;
        }
        aph += BK; apl += BK; bp0 += bstep; bp1 += bstep;
        if (NS > 1) {
            ah = *(const uint4*)aph;  al = *(const uint4*)apl;
            b00 = *(const float4*)bp0; b01 = *(const float4*)(bp0 + 4);
            b10 = *(const float4*)bp1; b11 = *(const float4*)(bp1 + 4);
            aph += BK; apl += BK; bp0 += bstep; bp1 += bstep;
        }
        __syncthreads();

        for (int k = 0; k < NS; ++k) {
            const int b  = k & 1;
            const int nb = b ^ 1;

            // ---- MMA on buf b ----
            __nv_bfloat16* sAhi = S_AHI(b); __nv_bfloat16* sAlo = S_ALO(b);
            __nv_bfloat16* sBhi = S_BHI(b); __nv_bfloat16* sBlo = S_BLO(b);
#pragma unroll
            for (int kk = 0; kk < 2; ++kk) {
                wmma::fragment<wmma::matrix_a, 16, 16, 16, __nv_bfloat16, wmma::row_major> ahi[2], alo[2];
#pragma unroll
                for (int m = 0; m < 2; ++m) {
                    const int ro = (warp_m * 32 + m * 16) * LDA + kk * 16;
                    wmma::load_matrix_sync(ahi[m], sAhi + ro, LDA);
                    wmma::load_matrix_sync(alo[m], sAlo + ro, LDA);
                }
#pragma unroll
                for (int n = 0; n < 2; ++n) {
                    const int co = (kk * 16) * LDB + warp_n * 32 + n * 16;
                    wmma::fragment<wmma::matrix_b, 16, 16, 16, __nv_bfloat16, wmma::row_major> bhi, blo;
                    wmma::load_matrix_sync(bhi, sBhi + co, LDB);
                    wmma::load_matrix_sync(blo, sBlo + co, LDB);
#pragma unroll
                    for (int m = 0; m < 2; ++m) {
                        wmma::mma_sync(acc[m][n], ahi[m], bhi, acc[m][n]);
                        wmma::mma_sync(acc[m][n], ahi[m], blo, acc[m][n]);
                        wmma::mma_sync(acc[m][n], alo[m], bhi, acc[m][n]);
                    }
                }
            }

            // ---- store tile k+1 (register-resident) into buf nb ----
            if (k + 1 < NS) {
                *(uint4*)(S_AHI(nb) + rA * LDA + cA) = ah;
                *(uint4*)(S_ALO(nb) + rA * LDA + cA) = al;
                uint4 hi, lo;
                split8(b00, b01, hi, lo);
                *(uint4*)(S_BHI(nb) + rB * LDB + cB) = hi;
                *(uint4*)(S_BLO(nb) + rB * LDB + cB) = lo;
                split8(b10, b11, hi, lo);
                *(uint4*)(S_BHI(nb) + (rB + 16) * LDB + cB) = hi;
                *(uint4*)(S_BLO(nb) + (rB + 16) * LDB + cB) = lo;
            }
            // ---- prefetch tile k+2 into registers ----
            if (k + 2 < NS) {
                ah = *(const uint4*)aph;  al = *(const uint4*)apl;
                b00 = *(const float4*)bp0; b01 = *(const float4*)(bp0 + 4);
                b10 = *(const float4*)bp1; b11 = *(const float4*)(bp1 + 4);
                aph += BK; apl += BK; bp0 += bstep; bp1 += bstep;
            }
            __syncthreads();
        }

        // ---- epilogue: stage via smem, predicated vector store ----
#pragma unroll
        for (int m = 0; m < 2; ++m)
#pragma unroll
            for (int n = 0; n < 2; ++n)
                wmma::store_matrix_sync(
                    sStage + (warp_m * 32 + m * 16) * LDB + warp_n * 32 + n * 16,
                    acc[m][n], LDB, wmma::mem_row_major);
        __syncthreads();
#pragma unroll
        for (int i = 0; i < 8; ++i) {
            int id = tid + i * NTHREADS;
            int r  = id >> 5;
            int c  = (id & 31) * 4;
            if (r < rows) {
                float4 v = *(const float4*)(sStage + r * LDB + c);
                *(float4*)(Out + (size_t)(row_base + r) * NTOT + n0 + c) = v;
            }
        }
        __syncthreads();
    }
#undef S_AHI
#undef S_ALO
#undef S_BHI
#undef S_BLO
}

// ---------------------------------------------------------------------------
extern "C" void kernel_launch(void* const* d_in, const int* in_sizes, int n_in,
                              void* d_out, int out_size) {
    const float* H  = (const float*)d_in[0];   // hidden_states [T, HS]
    const float* Wg = (const float*)d_in[1];   // gate_kernel   [E, HS, IMZ]
    const float* Wu = (const float*)d_in[2];   // up_kernel     [E, HS, IMZ]
    const float* Wd = (const float*)d_in[3];   // down_kernel   [E, IMZ, HS]
    const int*   gs = (const int*)d_in[4];     // group_sizes   [E]
    float* Out = (float*)d_out;                // [T, HS]

    cudaFuncSetAttribute(gemm_tc, cudaFuncAttributeMaxDynamicSharedMemorySize,
                         GEMM_SMEM);

    __nv_bfloat16 *Ahi_p = nullptr, *Alo_p = nullptr, *Ihi_p = nullptr, *Ilo_p = nullptr;
    float *gate_p = nullptr, *up_p = nullptr;
    cudaGetSymbolAddress((void**)&Ahi_p,  g_Ahi);
    cudaGetSymbolAddress((void**)&Alo_p,  g_Alo);
    cudaGetSymbolAddress((void**)&Ihi_p,  g_Ihi);
    cudaGetSymbolAddress((void**)&Ilo_p,  g_Ilo);
    cudaGetSymbolAddress((void**)&gate_p, g_gate);
    cudaGetSymbolAddress((void**)&up_p,   g_up);

    // Pre-split H into bf16 hi/lo planes.
    const int nH8 = (int)(((size_t)T_TOK * HS / 8 + 255) / 256);
    convert_H<<<nH8, 256>>>(H);

    // Gate + Up as ONE tile pool (704 tiles) for load balance.
    const int nt_gu = (IMZ / BN) * NE;   // 352
    gemm_tc<<<2 * nt_gu, NTHREADS, GEMM_SMEM>>>(
        Ahi_p, Alo_p, Wg, gate_p, Wu, up_p, gs, HS, IMZ, IMZ / BN, nt_gu);

    // SwiGLU, emitting bf16 hi/lo planes for the down GEMM.
    const int nI8 = (int)(((size_t)T_TOK * IMZ / 8 + 255) / 256);
    swiglu_kernel<<<nI8, 256>>>();

    // Down: 512 tiles.
    const int nt_dn = (HS / BN) * NE;    // 512
    gemm_tc<<<nt_dn, NTHREADS, GEMM_SMEM>>>(
        Ihi_p, Ilo_p, Wd, Out, Wd, Out, gs, IMZ, HS, HS / BN, nt_dn);
}